// round 9
// baseline (speedup 1.0000x reference)
#include <cuda_runtime.h>
#include <cuda_fp16.h>
#include <cstdint>

#define NSER 8
#define NLAY 4
#define HDIM 256
#define TILE_M 128
#define THREADS 512

// ---- smem layout (byte offsets from 1024-aligned base) ----
#define SM_A      0                     // 128x256 fp16 SW128 blocked atoms (65536)
#define SM_BUF0   65536                 // B k-half 0: 256j x 128k (65536)
#define SM_BUF1   131072                // B k-half 1 (65536)
#define SM_BIAS   196608                // per-group bias dbl buf: grp*2048 + slot*1024
#define SM_W0     200704                // 3072
#define SM_B0     203776                // 1024
#define SM_RED    204800                // per-group 1024 (2048 total)
#define SMEM_BYTES 207872

// Pre-swizzled fp16 weight tiles: [s*4+l] tiles, each 256(out j) x 256(in k)
__device__ __half g_Bw[(size_t)NSER * NLAY * HDIM * HDIM];

__device__ __forceinline__ uint32_t swz(uint32_t o) { return o ^ ((o >> 3) & 0x70); }

__device__ __forceinline__ uint32_t b_off(int j, int k) {
    uint32_t o = ((uint32_t)(j >> 3) + (uint32_t)(k >> 6) * 32u) * 1024u
               + (uint32_t)(j & 7) * 128u + (uint32_t)(k & 63) * 2u;
    return swz(o);
}

__device__ __forceinline__ uint32_t s2u(const void* p) {
    uint32_t a;
    asm("{ .reg .u64 t; cvta.to.shared.u64 t, %1; cvt.u32.u64 %0, t; }" : "=r"(a) : "l"(p));
    return a;
}

__device__ __forceinline__ float softplusf(float x) {
    float ax = fabsf(x), u, lg;
    asm("ex2.approx.ftz.f32 %0, %1;" : "=f"(u) : "f"(-1.4426950408889634f * ax));
    asm("lg2.approx.ftz.f32 %0, %1;" : "=f"(lg) : "f"(1.0f + u));
    return fmaxf(x, 0.0f) + 0.6931471805599453f * lg;
}

__device__ __forceinline__ __half2 sp2(float a, float b) {
    return __floats2half2_rn(softplusf(a), softplusf(b));
}

// ---- prep: fp32 Wh[s][l][k][j] (k=in, j=out) -> fp16 pre-swizzled B images ----
__global__ void prep_weights(const float* __restrict__ Wh) {
    int idx = blockIdx.x * blockDim.x + threadIdx.x;
    if (idx >= NSER * NLAY * HDIM * HDIM) return;
    int t = idx >> 16;
    int r = idx & 0xFFFF;
    int k = r >> 8;
    int j = r & 0xFF;
    float w = Wh[((size_t)t << 16) + (k << 8) + j];
    char* base = (char*)g_Bw + (size_t)t * 131072;
    *(__half*)(base + b_off(j, k)) = __float2half_rn(w);
}

__device__ __forceinline__ void ldsm_x4(uint32_t& r0, uint32_t& r1, uint32_t& r2,
                                        uint32_t& r3, uint32_t a) {
    asm volatile("ldmatrix.sync.aligned.m8n8.x4.shared.b16 {%0,%1,%2,%3}, [%4];"
                 : "=r"(r0), "=r"(r1), "=r"(r2), "=r"(r3) : "r"(a));
}
__device__ __forceinline__ void mma16816(float* c, uint32_t a0, uint32_t a1,
                                         uint32_t a2, uint32_t a3,
                                         uint32_t b0, uint32_t b1) {
    asm volatile(
        "mma.sync.aligned.m16n8k16.row.col.f32.f16.f16.f32 "
        "{%0,%1,%2,%3}, {%4,%5,%6,%7}, {%8,%9}, {%0,%1,%2,%3};"
        : "+f"(c[0]), "+f"(c[1]), "+f"(c[2]), "+f"(c[3])
        : "r"(a0), "r"(a1), "r"(a2), "r"(a3), "r"(b0), "r"(b1));
}

__device__ __forceinline__ void cp16(uint32_t saddr, const void* g) {
    asm volatile("cp.async.cg.shared.global [%0], [%1], 16;"
                 :: "r"(saddr), "l"(g) : "memory");
}
__device__ __forceinline__ void cp_commit() {
    asm volatile("cp.async.commit_group;" ::: "memory");
}
__device__ __forceinline__ void cp_wait0() {
    asm volatile("cp.async.wait_group 0;" ::: "memory");
}

#define GBAR(id) asm volatile("bar.sync %0, 256;" :: "r"(id) : "memory")

// full 128KB B tile (both halves, contiguous) by all 512 threads
__device__ __forceinline__ void issue_B_full(uint32_t sb, const char* g, int tid) {
    uint32_t d = sb + SM_BUF0 + (uint32_t)tid * 16u;
    #pragma unroll
    for (int i = 0; i < 16; i++)
        cp16(d + (uint32_t)i * 8192u, g + (size_t)tid * 16 + (size_t)i * 8192);
    cp_commit();
}
// one 64KB k-half by 256 threads (G1)
__device__ __forceinline__ void issue_B_half(uint32_t sb, uint32_t bufoff,
                                             const char* g, int gtid) {
    uint32_t d = sb + bufoff + (uint32_t)gtid * 16u;
    #pragma unroll
    for (int i = 0; i < 16; i++)
        cp16(d + (uint32_t)i * 4096u, g + (size_t)gtid * 16 + (size_t)i * 4096);
    cp_commit();
}

// one k-half of the layer MMA: 8 k-steps of 16 against the buffer at bufoff
__device__ __forceinline__ void mma_half(uint32_t sb, const uint32_t* a_rel,
    uint32_t a_xor, int akoff, uint32_t b_rel0, int bkoff, uint32_t b_xor,
    uint32_t bufoff, int khalf, float* acc)
{
    #pragma unroll
    for (int kss = 0; kss < 8; kss++) {
        uint32_t af[8];
        const int ka = khalf * 128 + kss * 16 + akoff;     // global k for A
        const uint32_t aterm = (uint32_t)((ka >> 6) * 16384)
                             + ((uint32_t)((ka & 63) * 2) ^ a_xor);
        ldsm_x4(af[0], af[1], af[2], af[3], sb + a_rel[0] + aterm);
        ldsm_x4(af[4], af[5], af[6], af[7], sb + a_rel[1] + aterm);
        const int kb = kss * 16 + bkoff;                   // buffer-local k
        uint32_t baddr = sb + bufoff + b_rel0 + (uint32_t)((kb >> 6) * 32768)
                       + ((uint32_t)((kb & 63) * 2) ^ b_xor);
        #pragma unroll
        for (int nf2 = 0; nf2 < 4; nf2++) {
            uint32_t br0, br1, br2, br3;
            ldsm_x4(br0, br1, br2, br3, baddr);
            baddr += 2048;
            mma16816(&acc[(nf2 * 2) * 4],         af[0], af[1], af[2], af[3], br0, br1);
            mma16816(&acc[(nf2 * 2 + 1) * 4],     af[0], af[1], af[2], af[3], br2, br3);
            mma16816(&acc[(8 + nf2 * 2) * 4],     af[4], af[5], af[6], af[7], br0, br1);
            mma16816(&acc[(8 + nf2 * 2 + 1) * 4], af[4], af[5], af[6], af[7], br2, br3);
        }
    }
}

__global__ void __launch_bounds__(THREADS, 1)
mlp_kernel(const float* __restrict__ coords,
           const float* __restrict__ W0,
           const float* __restrict__ b0,
           const float* __restrict__ bh,
           const float* __restrict__ Wout,
           const float* __restrict__ bout,
           float* __restrict__ out,
           int Ntot)
{
    extern __shared__ char smem_raw[];
    char* sm = (char*)(((uintptr_t)smem_raw + 1023) & ~(uintptr_t)1023);
    const uint32_t sb = s2u(sm);
    const int tid = threadIdx.x;
    const int s = blockIdx.y;
    const int base = blockIdx.x * TILE_M;

    const int grp  = tid >> 8;          // 0: rows 0-63, 1: rows 64-127
    const int gtid = tid & 255;
    const int gwid = (tid >> 5) & 7;
    const int ln   = tid & 31;
    const int wm   = gwid & 1;          // 2 M-tiles of 32 rows within group
    const int wn   = gwid >> 1;         // 4 N-tiles of 64 cols

    // ---- prologue: B(layer0) full copy + stage W0/b0/bias0 ----
    issue_B_full(sb, (const char*)(g_Bw + ((size_t)(s * NLAY) << 16)), tid);
    {
        const float* w0g = W0 + (size_t)s * 3 * HDIM;
        #pragma unroll
        for (int i = tid; i < 3 * HDIM; i += THREADS)
            ((float*)(sm + SM_W0))[i] = w0g[i];
        if (tid < HDIM)
            ((float*)(sm + SM_B0))[tid] = b0[(size_t)s * HDIM + tid];
        ((float*)(sm + SM_BIAS + grp * 2048))[gtid] =
            bh[(size_t)s * NLAY * HDIM + gtid];   // each group's slot 0
    }
    cp_wait0();
    __syncthreads();

    // ---- layer 0: group-private rows (grp*64 .. +63) ----
    {
        const int p = gtid & 63;
        const int q = gtid >> 6;          // 0..3 -> 64-col block
        const int m = grp * 64 + p;
        float c0 = 0.f, c1 = 0.f, c2 = 0.f;
        if (base + m < Ntot) {
            const float* cp = coords + (size_t)(base + m) * 3;
            c0 = cp[0]; c1 = cp[1]; c2 = cp[2];
        }
        const float* sw0 = (const float*)(sm + SM_W0);
        const float* sb0 = (const float*)(sm + SM_B0);
        const uint32_t arow = (uint32_t)((m >> 3) * 1024 + (m & 7) * 128)
                            + (uint32_t)(q * 16384);
        const uint32_t axor = (uint32_t)((m & 7) * 16);
        #pragma unroll 8
        for (int j = q * 64; j < q * 64 + 64; j += 2) {
            float v0 = sb0[j]   + c0 * sw0[j]   + c1 * sw0[256 + j]   + c2 * sw0[512 + j];
            float v1 = sb0[j+1] + c0 * sw0[j+1] + c1 * sw0[256 + j+1] + c2 * sw0[512 + j+1];
            uint32_t rel = arow + ((uint32_t)((j & 63) * 2) ^ axor);
            *(__half2*)(sm + SM_A + rel) = sp2(v0, v1);
        }
    }
    __syncthreads();

    // ---- per-lane fragment addressing (round-6-proven forms, grp offset) ----
    uint32_t a_rel[2];
    #pragma unroll
    for (int mf = 0; mf < 2; mf++) {
        int m = grp * 64 + wm * 32 + mf * 16 + (ln & 15);
        a_rel[mf] = (uint32_t)(SM_A + (m >> 3) * 1024 + (m & 7) * 128);
    }
    const uint32_t a_xor = (uint32_t)((ln & 7) * 16);
    const int akoff = (ln & 16) ? 8 : 0;
    const uint32_t b_rel0 = (uint32_t)(wn * 8192 + (ln & 7) * 128
                                       + ((ln & 16) ? 1024 : 0));
    const uint32_t b_xor = (uint32_t)((ln & 7) * 16);
    const int bkoff = (ln & 8) ? 8 : 0;

    // epilogue lane constants
    const int eml[2] = { grp * 64 + wm * 32 + 0 * 16 + (ln >> 2),
                         grp * 64 + wm * 32 + 1 * 16 + (ln >> 2) };

    float acc[64];

    for (int l = 0; l < NLAY; l++) {
        const char* gnext = (l < NLAY - 1)
            ? (const char*)(g_Bw + ((size_t)(s * NLAY + l + 1) << 16)) : (const char*)0;

        // ================= phase 1 =================
        if (grp == 0) {
            #pragma unroll
            for (int i = 0; i < 64; i++) acc[i] = 0.f;
            mma_half(sb, a_rel, a_xor, akoff, b_rel0, bkoff, b_xor,
                     SM_BUF0, 0, acc);
        } else {
            if (l > 0) {
                // stage bias for layer l into slot (l&1); epilogue(l-1) reads (l-1)&1
                ((float*)(sm + SM_BIAS + 2048 + (l & 1) * 1024))[gtid] =
                    bh[(size_t)(s * NLAY + l) * HDIM + gtid];
                const float* sbh = (const float*)(sm + SM_BIAS + 2048
                                                  + ((l - 1) & 1) * 1024);
                #pragma unroll
                for (int mf = 0; mf < 2; mf++) {
                    const int mlo = eml[mf];
                    const uint32_t alo = (uint32_t)(SM_A + (mlo >> 3) * 1024
                                                    + (mlo & 7) * 128);
                    const uint32_t xlo = (uint32_t)((mlo & 7) * 16);
                    #pragma unroll
                    for (int nf = 0; nf < 8; nf++) {
                        const int n0 = wn * 64 + nf * 8 + (ln & 3) * 2;
                        const float bv0 = sbh[n0], bv1 = sbh[n0 + 1];
                        const float* a4 = &acc[(mf * 8 + nf) * 4];
                        const uint32_t kt = (uint32_t)((n0 >> 6) * 16384)
                                          + ((uint32_t)((n0 & 63) * 2) ^ xlo);
                        *(__half2*)(sm + alo + kt)        = sp2(a4[0] + bv0, a4[1] + bv1);
                        *(__half2*)(sm + alo + 1024 + kt) = sp2(a4[2] + bv0, a4[3] + bv1);
                    }
                }
            }
        }
        __syncthreads();

        // ================= phase 2 =================
        if (grp == 0) {
            mma_half(sb, a_rel, a_xor, akoff, b_rel0, bkoff, b_xor,
                     SM_BUF1, 1, acc);
        } else {
            #pragma unroll
            for (int i = 0; i < 64; i++) acc[i] = 0.f;
            mma_half(sb, a_rel, a_xor, akoff, b_rel0, bkoff, b_xor,
                     SM_BUF0, 0, acc);
            if (l < NLAY - 1) {
                GBAR(6);            // ALL of G1 done reading BUF0 before refill
                issue_B_half(sb, SM_BUF0, gnext, gtid);     // refill k-half 0
            }
        }
        __syncthreads();

        // ================= phase 3 =================
        if (grp == 0) {
            if (l < NLAY - 1) {
                // stage bias for layer l+1 into slot ((l+1)&1)
                ((float*)(sm + SM_BIAS + ((l + 1) & 1) * 1024))[gtid] =
                    bh[(size_t)(s * NLAY + l + 1) * HDIM + gtid];
                const float* sbh = (const float*)(sm + SM_BIAS + (l & 1) * 1024);
                #pragma unroll
                for (int mf = 0; mf < 2; mf++) {
                    const int mlo = eml[mf];
                    const uint32_t alo = (uint32_t)(SM_A + (mlo >> 3) * 1024
                                                    + (mlo & 7) * 128);
                    const uint32_t xlo = (uint32_t)((mlo & 7) * 16);
                    #pragma unroll
                    for (int nf = 0; nf < 8; nf++) {
                        const int n0 = wn * 64 + nf * 8 + (ln & 3) * 2;
                        const float bv0 = sbh[n0], bv1 = sbh[n0 + 1];
                        const float* a4 = &acc[(mf * 8 + nf) * 4];
                        const uint32_t kt = (uint32_t)((n0 >> 6) * 16384)
                                          + ((uint32_t)((n0 & 63) * 2) ^ xlo);
                        *(__half2*)(sm + alo + kt)        = sp2(a4[0] + bv0, a4[1] + bv1);
                        *(__half2*)(sm + alo + 1024 + kt) = sp2(a4[2] + bv0, a4[3] + bv1);
                    }
                }
            } else {
                // G0 final: softplus * Wout, fused dot, rows 0-63
                const float* sbh = (const float*)(sm + SM_BIAS
                                                  + ((NLAY - 1) & 1) * 1024);
                const float* wog = Wout + (size_t)s * HDIM;
                float rsum[4];
                #pragma unroll
                for (int mf = 0; mf < 2; mf++) {
                    float lo = 0.f, hi = 0.f;
                    #pragma unroll
                    for (int nf = 0; nf < 8; nf++) {
                        const int n0 = wn * 64 + nf * 8 + (ln & 3) * 2;
                        const float bv0 = sbh[n0], bv1 = sbh[n0 + 1];
                        const float w0v = __ldg(wog + n0), w1v = __ldg(wog + n0 + 1);
                        const float* a4 = &acc[(mf * 8 + nf) * 4];
                        lo += softplusf(a4[0] + bv0) * w0v + softplusf(a4[1] + bv1) * w1v;
                        hi += softplusf(a4[2] + bv0) * w0v + softplusf(a4[3] + bv1) * w1v;
                    }
                    rsum[mf * 2] = lo; rsum[mf * 2 + 1] = hi;
                }
                #pragma unroll
                for (int i = 0; i < 4; i++) {
                    rsum[i] += __shfl_xor_sync(0xffffffffu, rsum[i], 1);
                    rsum[i] += __shfl_xor_sync(0xffffffffu, rsum[i], 2);
                }
                float* red = (float*)(sm + SM_RED);
                if ((ln & 3) == 0) {
                    #pragma unroll
                    for (int mf = 0; mf < 2; mf++) {
                        const int mloL = wm * 32 + mf * 16 + (ln >> 2);
                        red[wn * 64 + mloL]     = rsum[mf * 2];
                        red[wn * 64 + mloL + 8] = rsum[mf * 2 + 1];
                    }
                }
                GBAR(3);
                if (gtid < 64 && base + gtid < Ntot) {
                    float v = red[gtid] + red[64 + gtid] + red[128 + gtid]
                            + red[192 + gtid] + __ldg(bout + s);
                    out[(size_t)(base + gtid) * NSER + s] = v;
                }
            }
        } else {
            mma_half(sb, a_rel, a_xor, akoff, b_rel0, bkoff, b_xor,
                     SM_BUF1, 1, acc);
            if (l < NLAY - 1) {
                GBAR(7);            // ALL of G1 done reading BUF1 before refill
                issue_B_half(sb, SM_BUF1, gnext + 65536, gtid);  // refill k-half 1
                cp_wait0();
            }
        }
        __syncthreads();
    }

    // ---- tail: G1's final epilogue (rows 64-127) ----
    if (grp == 1) {
        const float* sbh = (const float*)(sm + SM_BIAS + 2048
                                          + ((NLAY - 1) & 1) * 1024);
        const float* wog = Wout + (size_t)s * HDIM;
        float rsum[4];
        #pragma unroll
        for (int mf = 0; mf < 2; mf++) {
            float lo = 0.f, hi = 0.f;
            #pragma unroll
            for (int nf = 0; nf < 8; nf++) {
                const int n0 = wn * 64 + nf * 8 + (ln & 3) * 2;
                const float bv0 = sbh[n0], bv1 = sbh[n0 + 1];
                const float w0v = __ldg(wog + n0), w1v = __ldg(wog + n0 + 1);
                const float* a4 = &acc[(mf * 8 + nf) * 4];
                lo += softplusf(a4[0] + bv0) * w0v + softplusf(a4[1] + bv1) * w1v;
                hi += softplusf(a4[2] + bv0) * w0v + softplusf(a4[3] + bv1) * w1v;
            }
            rsum[mf * 2] = lo; rsum[mf * 2 + 1] = hi;
        }
        #pragma unroll
        for (int i = 0; i < 4; i++) {
            rsum[i] += __shfl_xor_sync(0xffffffffu, rsum[i], 1);
            rsum[i] += __shfl_xor_sync(0xffffffffu, rsum[i], 2);
        }
        float* red = (float*)(sm + SM_RED + 1024);
        if ((ln & 3) == 0) {
            #pragma unroll
            for (int mf = 0; mf < 2; mf++) {
                const int mloL = wm * 32 + mf * 16 + (ln >> 2);
                red[wn * 64 + mloL]     = rsum[mf * 2];
                red[wn * 64 + mloL + 8] = rsum[mf * 2 + 1];
            }
        }
        GBAR(4);
        if (gtid < 64) {
            const int m = 64 + gtid;
            if (base + m < Ntot) {
                float v = red[gtid] + red[64 + gtid] + red[128 + gtid]
                        + red[192 + gtid] + __ldg(bout + s);
                out[(size_t)(base + m) * NSER + s] = v;
            }
        }
    }
}

extern "C" void kernel_launch(void* const* d_in, const int* in_sizes, int n_in,
                              void* d_out, int out_size) {
    const float* coords = (const float*)d_in[0];
    const float* W0     = (const float*)d_in[1];
    const float* b0     = (const float*)d_in[2];
    const float* Wh     = (const float*)d_in[3];
    const float* bh     = (const float*)d_in[4];
    const float* Wout   = (const float*)d_in[5];
    const float* bout   = (const float*)d_in[6];
    const int Npts = in_sizes[0] / 3;

    cudaFuncSetAttribute(mlp_kernel, cudaFuncAttributeMaxDynamicSharedMemorySize,
                         SMEM_BYTES);

    const int wtotal = NSER * NLAY * HDIM * HDIM;
    prep_weights<<<(wtotal + 255) / 256, 256>>>(Wh);

    dim3 grid((Npts + TILE_M - 1) / TILE_M, NSER);
    mlp_kernel<<<grid, THREADS, SMEM_BYTES>>>(coords, W0, b0, bh, Wout, bout,
                                              (float*)d_out, Npts);

    long long need = (long long)Npts * NSER + (long long)Npts * 3;
    if ((long long)out_size >= need) {
        cudaMemcpyAsync((float*)d_out + (size_t)Npts * NSER, coords,
                        sizeof(float) * (size_t)Npts * 3,
                        cudaMemcpyDeviceToDevice, 0);
    }
}

// round 10
// speedup vs baseline: 1.1508x; 1.1508x over previous
#include <cuda_runtime.h>
#include <cuda_fp16.h>
#include <cstdint>

#define NSER 8
#define NLAY 4
#define HDIM 256
#define TILE_M 64
#define THREADS 256

// ---- smem layout (byte offsets from 1024-aligned base) ----
#define SM_A      0                     // 64x256 fp16 SW128 blocked atoms (32768)
#define SM_BB     32768                 // B chunk double buffer: 2 x 32768
#define SM_BIAS   98304                 // bias double buffer 2 x 1024
#define SM_W0     100352                // 3072
#define SM_B0     103424                // 1024
#define SM_RED    104448                // 256 floats (1024)
#define SMEM_BYTES (105472 + 1024)

// Pre-swizzled fp16 weight tiles: [s*4+l] tiles, each 256(out j) x 256(in k).
// Image = 4 contiguous 32KB chunks per layer (one per 64-k block).
__device__ __half g_Bw[(size_t)NSER * NLAY * HDIM * HDIM];

__device__ __forceinline__ uint32_t swz(uint32_t o) { return o ^ ((o >> 3) & 0x70); }

__device__ __forceinline__ uint32_t b_off(int j, int k) {
    uint32_t o = ((uint32_t)(j >> 3) + (uint32_t)(k >> 6) * 32u) * 1024u
               + (uint32_t)(j & 7) * 128u + (uint32_t)(k & 63) * 2u;
    return swz(o);
}

__device__ __forceinline__ uint32_t s2u(const void* p) {
    uint32_t a;
    asm("{ .reg .u64 t; cvta.to.shared.u64 t, %1; cvt.u32.u64 %0, t; }" : "=r"(a) : "l"(p));
    return a;
}

__device__ __forceinline__ float softplusf(float x) {
    float ax = fabsf(x), u, lg;
    asm("ex2.approx.ftz.f32 %0, %1;" : "=f"(u) : "f"(-1.4426950408889634f * ax));
    asm("lg2.approx.ftz.f32 %0, %1;" : "=f"(lg) : "f"(1.0f + u));
    return fmaxf(x, 0.0f) + 0.6931471805599453f * lg;
}

__device__ __forceinline__ __half2 sp2(float a, float b) {
    return __floats2half2_rn(softplusf(a), softplusf(b));
}

// ---- prep: fp32 Wh[s][l][k][j] (k=in, j=out) -> fp16 pre-swizzled B images ----
__global__ void prep_weights(const float* __restrict__ Wh) {
    int idx = blockIdx.x * blockDim.x + threadIdx.x;
    if (idx >= NSER * NLAY * HDIM * HDIM) return;
    int t = idx >> 16;
    int r = idx & 0xFFFF;
    int k = r >> 8;
    int j = r & 0xFF;
    float w = Wh[((size_t)t << 16) + (k << 8) + j];
    char* base = (char*)g_Bw + (size_t)t * 131072;
    *(__half*)(base + b_off(j, k)) = __float2half_rn(w);
}

__device__ __forceinline__ void ldsm_x4(uint32_t& r0, uint32_t& r1, uint32_t& r2,
                                        uint32_t& r3, uint32_t a) {
    asm volatile("ldmatrix.sync.aligned.m8n8.x4.shared.b16 {%0,%1,%2,%3}, [%4];"
                 : "=r"(r0), "=r"(r1), "=r"(r2), "=r"(r3) : "r"(a));
}
__device__ __forceinline__ void mma16816(float* c, uint32_t a0, uint32_t a1,
                                         uint32_t a2, uint32_t a3,
                                         uint32_t b0, uint32_t b1) {
    asm volatile(
        "mma.sync.aligned.m16n8k16.row.col.f32.f16.f16.f32 "
        "{%0,%1,%2,%3}, {%4,%5,%6,%7}, {%8,%9}, {%0,%1,%2,%3};"
        : "+f"(c[0]), "+f"(c[1]), "+f"(c[2]), "+f"(c[3])
        : "r"(a0), "r"(a1), "r"(a2), "r"(a3), "r"(b0), "r"(b1));
}

__device__ __forceinline__ void cp16(uint32_t saddr, const void* g) {
    asm volatile("cp.async.cg.shared.global [%0], [%1], 16;"
                 :: "r"(saddr), "l"(g) : "memory");
}
__device__ __forceinline__ void cp_commit() {
    asm volatile("cp.async.commit_group;" ::: "memory");
}
__device__ __forceinline__ void cp_wait1() {
    asm volatile("cp.async.wait_group 1;" ::: "memory");
}
__device__ __forceinline__ void cp_wait0() {
    asm volatile("cp.async.wait_group 0;" ::: "memory");
}

// copy one 32KB chunk (64 k-cols of B) by 256 threads: 8 x 16B per thread
__device__ __forceinline__ void issue_chunk(uint32_t sb, uint32_t bufoff,
                                            const char* g, int tid) {
    uint32_t d = sb + bufoff + (uint32_t)tid * 16u;
    #pragma unroll
    for (int i = 0; i < 8; i++)
        cp16(d + (uint32_t)i * 4096u, g + (size_t)tid * 16 + (size_t)i * 4096);
    cp_commit();
}

// one quarter-k of the layer MMA: 4 k-steps of 16 against the chunk at bufoff
__device__ __forceinline__ void mma_chunk(uint32_t sb, const uint32_t* a_rel,
    uint32_t a_xor, int akoff, uint32_t b_rel0, int bkoff, uint32_t b_xor,
    uint32_t bufoff, int kq, float* acc)
{
    #pragma unroll
    for (int kss = 0; kss < 4; kss++) {
        uint32_t af[8];
        const int ka = kq * 64 + kss * 16 + akoff;         // global k for A
        const uint32_t aterm = (uint32_t)((ka >> 6) * 8192)
                             + ((uint32_t)((ka & 63) * 2) ^ a_xor);
        ldsm_x4(af[0], af[1], af[2], af[3], sb + a_rel[0] + aterm);
        ldsm_x4(af[4], af[5], af[6], af[7], sb + a_rel[1] + aterm);
        const int kb = kss * 16 + bkoff;                   // chunk-local k (<64)
        uint32_t baddr = sb + bufoff + b_rel0
                       + ((uint32_t)(kb * 2) ^ b_xor);
        #pragma unroll
        for (int nf2 = 0; nf2 < 4; nf2++) {
            uint32_t br0, br1, br2, br3;
            ldsm_x4(br0, br1, br2, br3, baddr);
            baddr += 2048;
            mma16816(&acc[(nf2 * 2) * 4],         af[0], af[1], af[2], af[3], br0, br1);
            mma16816(&acc[(nf2 * 2 + 1) * 4],     af[0], af[1], af[2], af[3], br2, br3);
            mma16816(&acc[(8 + nf2 * 2) * 4],     af[4], af[5], af[6], af[7], br0, br1);
            mma16816(&acc[(8 + nf2 * 2 + 1) * 4], af[4], af[5], af[6], af[7], br2, br3);
        }
    }
}

__global__ void __launch_bounds__(THREADS, 2)
mlp_kernel(const float* __restrict__ coords,
           const float* __restrict__ W0,
           const float* __restrict__ b0,
           const float* __restrict__ bh,
           const float* __restrict__ Wout,
           const float* __restrict__ bout,
           float* __restrict__ out,
           int Ntot)
{
    extern __shared__ char smem_raw[];
    char* sm = (char*)(((uintptr_t)smem_raw + 1023) & ~(uintptr_t)1023);
    const uint32_t sb = s2u(sm);
    const int tid = threadIdx.x;
    const int s = blockIdx.y;
    const int base = blockIdx.x * TILE_M;

    const int wid = tid >> 5, ln = tid & 31;
    const int wm = wid & 1;             // 2 M-tiles of 32 rows
    const int wn = wid >> 1;            // 4 N-tiles of 64 cols

    const char* tile_base = (const char*)(g_Bw + ((size_t)(s * NLAY) << 16));

    // ---- prologue: chunk 0 + stage W0/b0/bias0 ----
    issue_chunk(sb, SM_BB, tile_base, tid);
    {
        const float* w0g = W0 + (size_t)s * 3 * HDIM;
        #pragma unroll
        for (int i = tid; i < 3 * HDIM; i += THREADS)
            ((float*)(sm + SM_W0))[i] = w0g[i];
        ((float*)(sm + SM_B0))[tid] = b0[(size_t)s * HDIM + tid];
        ((float*)(sm + SM_BIAS))[tid] = bh[(size_t)s * NLAY * HDIM + tid];
    }

    // ---- layer 0: [64x3]@[3x256] + softplus -> swizzled A tile ----
    __syncthreads();   // W0/b0 staged
    {
        const int p = tid & 63;
        const int q = tid >> 6;           // 0..3 -> 64-col k-block
        float c0 = 0.f, c1 = 0.f, c2 = 0.f;
        if (base + p < Ntot) {
            const float* cp = coords + (size_t)(base + p) * 3;
            c0 = cp[0]; c1 = cp[1]; c2 = cp[2];
        }
        const float* sw0 = (const float*)(sm + SM_W0);
        const float* sb0 = (const float*)(sm + SM_B0);
        const uint32_t arow = (uint32_t)((p >> 3) * 1024 + (p & 7) * 128)
                            + (uint32_t)(q * 8192);
        const uint32_t axor = (uint32_t)((p & 7) * 16);
        #pragma unroll 8
        for (int j = q * 64; j < q * 64 + 64; j += 2) {
            float v0 = sb0[j]   + c0 * sw0[j]   + c1 * sw0[256 + j]   + c2 * sw0[512 + j];
            float v1 = sb0[j+1] + c0 * sw0[j+1] + c1 * sw0[256 + j+1] + c2 * sw0[512 + j+1];
            uint32_t rel = arow + ((uint32_t)((j & 63) * 2) ^ axor);
            *(__half2*)(sm + SM_A + rel) = sp2(v0, v1);
        }
    }

    // ---- per-lane fragment addressing ----
    uint32_t a_rel[2];
    #pragma unroll
    for (int mf = 0; mf < 2; mf++) {
        int m = wm * 32 + mf * 16 + (ln & 15);
        a_rel[mf] = (uint32_t)(SM_A + (m >> 3) * 1024 + (m & 7) * 128);
    }
    const uint32_t a_xor = (uint32_t)((ln & 7) * 16);
    const int akoff = (ln & 16) ? 8 : 0;
    const uint32_t b_rel0 = (uint32_t)(wn * 8192 + (ln & 7) * 128
                                       + ((ln & 16) ? 1024 : 0));
    const uint32_t b_xor = (uint32_t)((ln & 7) * 16);
    const int bkoff = (ln & 8) ? 8 : 0;

    const int eml[2] = { wm * 32 + 0 * 16 + (ln >> 2),
                         wm * 32 + 1 * 16 + (ln >> 2) };

    float acc[64];

    for (int l = 0; l < NLAY; l++) {
        #pragma unroll
        for (int i = 0; i < 64; i++) acc[i] = 0.f;

        #pragma unroll
        for (int kq = 0; kq < 4; kq++) {
            const int g = l * 4 + kq;                  // global chunk step
            if (g < 15)
                issue_chunk(sb, SM_BB + (uint32_t)(((g + 1) & 1) * 32768),
                            tile_base + (size_t)(g + 1) * 32768, tid);
            if (g < 15) cp_wait1(); else cp_wait0();   // chunk g landed
            __syncthreads();                           // visibility (+ A ready)
            mma_chunk(sb, a_rel, a_xor, akoff, b_rel0, bkoff, b_xor,
                      SM_BB + (uint32_t)((g & 1) * 32768), kq, acc);
            __syncthreads();                           // all reads done pre-refill
        }

        if (l < NLAY - 1) {
            // stage next bias; epilogue: bias + softplus -> A (in place)
            ((float*)(sm + SM_BIAS + ((l + 1) & 1) * 1024))[tid] =
                bh[(size_t)(s * NLAY + l + 1) * HDIM + tid];
            const float* sbh = (const float*)(sm + SM_BIAS + (l & 1) * 1024);
            #pragma unroll
            for (int mf = 0; mf < 2; mf++) {
                const int mlo = eml[mf];
                const uint32_t alo = (uint32_t)(SM_A + (mlo >> 3) * 1024
                                                + (mlo & 7) * 128);
                const uint32_t xlo = (uint32_t)((mlo & 7) * 16);
                #pragma unroll
                for (int nf = 0; nf < 8; nf++) {
                    const int n0 = wn * 64 + nf * 8 + (ln & 3) * 2;
                    const float bv0 = sbh[n0], bv1 = sbh[n0 + 1];
                    const float* a4 = &acc[(mf * 8 + nf) * 4];
                    const uint32_t kt = (uint32_t)((n0 >> 6) * 8192)
                                      + ((uint32_t)((n0 & 63) * 2) ^ xlo);
                    *(__half2*)(sm + alo + kt)        = sp2(a4[0] + bv0, a4[1] + bv1);
                    *(__half2*)(sm + alo + 1024 + kt) = sp2(a4[2] + bv0, a4[3] + bv1);
                }
            }
            // NOTE: next layer's first __syncthreads() orders these A writes
            // before any warp's ldmatrix reads.
        } else {
            // final layer: softplus * Wout, fused 256->1 dot
            const float* sbh = (const float*)(sm + SM_BIAS + ((NLAY - 1) & 1) * 1024);
            const float* wog = Wout + (size_t)s * HDIM;
            float rsum[4];
            #pragma unroll
            for (int mf = 0; mf < 2; mf++) {
                float lo = 0.f, hi = 0.f;
                #pragma unroll
                for (int nf = 0; nf < 8; nf++) {
                    const int n0 = wn * 64 + nf * 8 + (ln & 3) * 2;
                    const float bv0 = sbh[n0], bv1 = sbh[n0 + 1];
                    const float w0v = __ldg(wog + n0), w1v = __ldg(wog + n0 + 1);
                    const float* a4 = &acc[(mf * 8 + nf) * 4];
                    lo += softplusf(a4[0] + bv0) * w0v + softplusf(a4[1] + bv1) * w1v;
                    hi += softplusf(a4[2] + bv0) * w0v + softplusf(a4[3] + bv1) * w1v;
                }
                rsum[mf * 2] = lo; rsum[mf * 2 + 1] = hi;
            }
            #pragma unroll
            for (int i = 0; i < 4; i++) {
                rsum[i] += __shfl_xor_sync(0xffffffffu, rsum[i], 1);
                rsum[i] += __shfl_xor_sync(0xffffffffu, rsum[i], 2);
            }
            float* red = (float*)(sm + SM_RED);
            if ((ln & 3) == 0) {
                #pragma unroll
                for (int mf = 0; mf < 2; mf++) {
                    const int mloL = eml[mf] & 63;
                    red[wn * 64 + mloL]     = rsum[mf * 2];
                    red[wn * 64 + mloL + 8] = rsum[mf * 2 + 1];
                }
            }
            __syncthreads();
            if (tid < 64 && base + tid < Ntot) {
                float v = red[tid] + red[64 + tid] + red[128 + tid]
                        + red[192 + tid] + __ldg(bout + s);
                out[(size_t)(base + tid) * NSER + s] = v;
            }
        }
    }
}

extern "C" void kernel_launch(void* const* d_in, const int* in_sizes, int n_in,
                              void* d_out, int out_size) {
    const float* coords = (const float*)d_in[0];
    const float* W0     = (const float*)d_in[1];
    const float* b0     = (const float*)d_in[2];
    const float* Wh     = (const float*)d_in[3];
    const float* bh     = (const float*)d_in[4];
    const float* Wout   = (const float*)d_in[5];
    const float* bout   = (const float*)d_in[6];
    const int Npts = in_sizes[0] / 3;

    cudaFuncSetAttribute(mlp_kernel, cudaFuncAttributeMaxDynamicSharedMemorySize,
                         SMEM_BYTES);

    const int wtotal = NSER * NLAY * HDIM * HDIM;
    prep_weights<<<(wtotal + 255) / 256, 256>>>(Wh);

    dim3 grid((Npts + TILE_M - 1) / TILE_M, NSER);
    mlp_kernel<<<grid, THREADS, SMEM_BYTES>>>(coords, W0, b0, bh, Wout, bout,
                                              (float*)d_out, Npts);

    long long need = (long long)Npts * NSER + (long long)Npts * 3;
    if ((long long)out_size >= need) {
        cudaMemcpyAsync((float*)d_out + (size_t)Npts * NSER, coords,
                        sizeof(float) * (size_t)Npts * 3,
                        cudaMemcpyDeviceToDevice, 0);
    }
}